// round 12
// baseline (speedup 1.0000x reference)
#include <cuda_runtime.h>
#include <cuda_fp16.h>
#include <cstdint>

// Shapes: white/black [4096,32] i32, stm [4096] i32, emb [40960,2048] f32,
// W1 [128,4096] f32, b1[128], W2[1,128], b2[1]; out [4096,1] f32.
#define BATCH 4096
#define LFEAT 32
#define DIM   2048
#define NFEAT 40960
#define POUT  256         // cols 0..127: white-half proj, 128..255: black-half proj

// GEMM tiling
#define BM 128
#define BN 256
#define BK 32
#define KSTEPS (DIM / BK)         // 64
#define LDA 40                    // padded row (halves): 80 B, 16B-aligned
#define A_TILE_H (BM * LDA)       // 5120 halves
#define B_TILE_H (BN * LDA)       // 10240 halves
// per-stage smem layout (halves): [Ahi][Alo][Bh][Bl]
#define OFF_AHI 0
#define OFF_ALO (OFF_AHI + A_TILE_H)
#define OFF_BH  (OFF_ALO + A_TILE_H)
#define OFF_BL  (OFF_BH + B_TILE_H)
#define STAGE_H (OFF_BL + B_TILE_H)       // 30720 halves = 61440 B
#define SMEM_SZ (2 * STAGE_H * 2)         // 122880 B

// ---------------- scratch (static; no allocation APIs) ----------------
__device__ float  g_P[(size_t)NFEAT * POUT];     // 42 MB projection table
__device__ __half g_Bt[(size_t)POUT * 4096];     // 2 MB: Bt[n][k], k<2048 hi, k>=2048 lo

// ---------------- small helpers ----------------
__device__ __forceinline__ void cpasync16(uint32_t dst, const void* src) {
    asm volatile("cp.async.cg.shared.global [%0], [%1], 16;\n" :: "r"(dst), "l"(src));
}
__device__ __forceinline__ void cp_commit() { asm volatile("cp.async.commit_group;\n"); }
__device__ __forceinline__ void cp_wait0()  { asm volatile("cp.async.wait_group 0;\n"); }

__device__ __forceinline__ void mma16816(float* c, const uint32_t* a, const uint32_t* b) {
    asm volatile(
        "mma.sync.aligned.m16n8k16.row.col.f32.f16.f16.f32 "
        "{%0,%1,%2,%3}, {%4,%5,%6,%7}, {%8,%9}, {%0,%1,%2,%3};\n"
        : "+f"(c[0]), "+f"(c[1]), "+f"(c[2]), "+f"(c[3])
        : "r"(a[0]), "r"(a[1]), "r"(a[2]), "r"(a[3]), "r"(b[0]), "r"(b[1]));
}

// ---------------------------------------------------------------------------
// K0: build Bt[n][k] fp16. For k<2048: hi(W1row); for k>=2048: lo residual.
//   n<128  -> W1[n][k']        (white half, k' = k mod 2048)
//   n>=128 -> W1[n-128][k'+2048] (black half)
// ---------------------------------------------------------------------------
__global__ void __launch_bounds__(256) splitW1_kernel(const float* __restrict__ W1) {
    int base = (blockIdx.x * 256 + threadIdx.x) * 16;     // 16 consecutive k of one n
    int n = base >> 12;           // /4096
    int k0 = base & 4095;
    bool lo_part = (k0 >= DIM);
    int kk = lo_part ? (k0 - DIM) : k0;
    const float* src = (n < 128) ? (W1 + (size_t)n * 4096 + kk)
                                 : (W1 + (size_t)(n - 128) * 4096 + DIM + kk);
    __half* dst = g_Bt + (size_t)n * 4096 + k0;
    #pragma unroll
    for (int i = 0; i < 16; i++) {
        float x = src[i];
        __half h = __float2half_rn(x);
        dst[i] = lo_part ? __float2half_rn(x - __half2float(h)) : h;
    }
}

// ---------------------------------------------------------------------------
// K1: P = emb @ Bt' with 3-term fp16 split, fp32 accumulate.
// grid = 320 (M tiles), 256 threads (8 warps: 2m x 4n), double-buffered smem.
// ---------------------------------------------------------------------------
__global__ void __launch_bounds__(256) pgemm_kernel(const float* __restrict__ emb) {
    extern __shared__ __align__(16) __half s[];
    const int tid  = threadIdx.x;
    const int lane = tid & 31;
    const int wid  = tid >> 5;
    const int wm   = wid >> 2;          // 0..1
    const int wn   = wid & 3;           // 0..3
    const int m0   = blockIdx.x * BM;

    // A load mapping: row = tid/2, 16-float half = tid&1
    const int arow  = tid >> 1;
    const int ahalf = tid & 1;
    const float* aptr = emb + (size_t)(m0 + arow) * DIM + ahalf * 16;
    // B cp.async mapping: chunk q = tid&3 (16B), row group = tid>>2 (+r*64)
    const int bq = tid & 3;
    const int bn0 = tid >> 2;

    float acc[4][8][4];
    #pragma unroll
    for (int mt = 0; mt < 4; mt++)
        #pragma unroll
        for (int nt = 0; nt < 8; nt++)
            #pragma unroll
            for (int i = 0; i < 4; i++) acc[mt][nt][i] = 0.f;

    float areg[16];

    // ---- prologue: stage 0 ----
    {
        const float4* p = reinterpret_cast<const float4*>(aptr);
        #pragma unroll
        for (int i = 0; i < 4; i++) {
            float4 v = p[i];
            areg[i*4+0]=v.x; areg[i*4+1]=v.y; areg[i*4+2]=v.z; areg[i*4+3]=v.w;
        }
        #pragma unroll
        for (int r = 0; r < 4; r++) {
            int n = bn0 + r * 64;
            uint32_t dh = (uint32_t)__cvta_generic_to_shared(&s[OFF_BH + n * LDA + bq * 8]);
            uint32_t dl = (uint32_t)__cvta_generic_to_shared(&s[OFF_BL + n * LDA + bq * 8]);
            cpasync16(dh, g_Bt + (size_t)n * 4096 + bq * 8);
            cpasync16(dl, g_Bt + (size_t)n * 4096 + DIM + bq * 8);
        }
        cp_commit();
        // convert + STS A stage 0
        __half hi[16], lo[16];
        #pragma unroll
        for (int i = 0; i < 16; i++) {
            hi[i] = __float2half_rn(areg[i]);
            lo[i] = __float2half_rn(areg[i] - __half2float(hi[i]));
        }
        uint4* dsth = reinterpret_cast<uint4*>(&s[OFF_AHI + arow * LDA + ahalf * 16]);
        uint4* dstl = reinterpret_cast<uint4*>(&s[OFF_ALO + arow * LDA + ahalf * 16]);
        dsth[0] = reinterpret_cast<uint4*>(hi)[0]; dsth[1] = reinterpret_cast<uint4*>(hi)[1];
        dstl[0] = reinterpret_cast<uint4*>(lo)[0]; dstl[1] = reinterpret_cast<uint4*>(lo)[1];
    }

    for (int kk = 0; kk < KSTEPS; kk++) {
        const int sb  = (kk & 1) * STAGE_H;
        const int sb1 = ((kk + 1) & 1) * STAGE_H;

        cp_wait0();
        __syncthreads();

        // issue next-stage loads (hidden under compute)
        if (kk < KSTEPS - 1) {
            const float4* p = reinterpret_cast<const float4*>(aptr + (kk + 1) * BK);
            #pragma unroll
            for (int i = 0; i < 4; i++) {
                float4 v = p[i];
                areg[i*4+0]=v.x; areg[i*4+1]=v.y; areg[i*4+2]=v.z; areg[i*4+3]=v.w;
            }
            #pragma unroll
            for (int r = 0; r < 4; r++) {
                int n = bn0 + r * 64;
                uint32_t dh = (uint32_t)__cvta_generic_to_shared(&s[sb1 + OFF_BH + n * LDA + bq * 8]);
                uint32_t dl = (uint32_t)__cvta_generic_to_shared(&s[sb1 + OFF_BL + n * LDA + bq * 8]);
                cpasync16(dh, g_Bt + (size_t)n * 4096 + (kk + 1) * BK + bq * 8);
                cpasync16(dl, g_Bt + (size_t)n * 4096 + DIM + (kk + 1) * BK + bq * 8);
            }
            cp_commit();
        }

        // ---- compute stage kk ----
        #pragma unroll
        for (int h = 0; h < 2; h++) {
            const int c = h * 16 + (lane & 3) * 2;
            uint32_t ah[4][4], al[4][4], bh[8][2], bl[8][2];
            #pragma unroll
            for (int mt = 0; mt < 4; mt++) {
                int r = wm * 64 + mt * 16 + (lane >> 2);
                ah[mt][0] = *reinterpret_cast<const uint32_t*>(&s[sb + OFF_AHI + r * LDA + c]);
                ah[mt][1] = *reinterpret_cast<const uint32_t*>(&s[sb + OFF_AHI + (r + 8) * LDA + c]);
                ah[mt][2] = *reinterpret_cast<const uint32_t*>(&s[sb + OFF_AHI + r * LDA + c + 8]);
                ah[mt][3] = *reinterpret_cast<const uint32_t*>(&s[sb + OFF_AHI + (r + 8) * LDA + c + 8]);
            }
            #pragma unroll
            for (int nt = 0; nt < 8; nt++) {
                int n = wn * 64 + nt * 8 + (lane >> 2);
                bh[nt][0] = *reinterpret_cast<const uint32_t*>(&s[sb + OFF_BH + n * LDA + c]);
                bh[nt][1] = *reinterpret_cast<const uint32_t*>(&s[sb + OFF_BH + n * LDA + c + 8]);
            }
            #pragma unroll
            for (int mt = 0; mt < 4; mt++)
                #pragma unroll
                for (int nt = 0; nt < 8; nt++) mma16816(acc[mt][nt], ah[mt], bh[nt]);
            #pragma unroll
            for (int mt = 0; mt < 4; mt++) {
                int r = wm * 64 + mt * 16 + (lane >> 2);
                al[mt][0] = *reinterpret_cast<const uint32_t*>(&s[sb + OFF_ALO + r * LDA + c]);
                al[mt][1] = *reinterpret_cast<const uint32_t*>(&s[sb + OFF_ALO + (r + 8) * LDA + c]);
                al[mt][2] = *reinterpret_cast<const uint32_t*>(&s[sb + OFF_ALO + r * LDA + c + 8]);
                al[mt][3] = *reinterpret_cast<const uint32_t*>(&s[sb + OFF_ALO + (r + 8) * LDA + c + 8]);
            }
            #pragma unroll
            for (int mt = 0; mt < 4; mt++)
                #pragma unroll
                for (int nt = 0; nt < 8; nt++) mma16816(acc[mt][nt], al[mt], bh[nt]);
            #pragma unroll
            for (int nt = 0; nt < 8; nt++) {
                int n = wn * 64 + nt * 8 + (lane >> 2);
                bl[nt][0] = *reinterpret_cast<const uint32_t*>(&s[sb + OFF_BL + n * LDA + c]);
                bl[nt][1] = *reinterpret_cast<const uint32_t*>(&s[sb + OFF_BL + n * LDA + c + 8]);
            }
            #pragma unroll
            for (int mt = 0; mt < 4; mt++)
                #pragma unroll
                for (int nt = 0; nt < 8; nt++) mma16816(acc[mt][nt], ah[mt], bl[nt]);
        }

        // convert + STS A for next stage (A region of s^1; race-free vs compute of s)
        if (kk < KSTEPS - 1) {
            __half hi[16], lo[16];
            #pragma unroll
            for (int i = 0; i < 16; i++) {
                hi[i] = __float2half_rn(areg[i]);
                lo[i] = __float2half_rn(areg[i] - __half2float(hi[i]));
            }
            uint4* dsth = reinterpret_cast<uint4*>(&s[sb1 + OFF_AHI + arow * LDA + ahalf * 16]);
            uint4* dstl = reinterpret_cast<uint4*>(&s[sb1 + OFF_ALO + arow * LDA + ahalf * 16]);
            dsth[0] = reinterpret_cast<uint4*>(hi)[0]; dsth[1] = reinterpret_cast<uint4*>(hi)[1];
            dstl[0] = reinterpret_cast<uint4*>(lo)[0]; dstl[1] = reinterpret_cast<uint4*>(lo)[1];
        }
    }

    // ---- epilogue: write P ----
    #pragma unroll
    for (int mt = 0; mt < 4; mt++) {
        int r0 = m0 + wm * 64 + mt * 16 + (lane >> 2);
        #pragma unroll
        for (int nt = 0; nt < 8; nt++) {
            int cc = wn * 64 + nt * 8 + (lane & 3) * 2;
            *reinterpret_cast<float2*>(g_P + (size_t)r0 * POUT + cc) =
                make_float2(acc[mt][nt][0], acc[mt][nt][1]);
            *reinterpret_cast<float2*>(g_P + (size_t)(r0 + 8) * POUT + cc) =
                make_float2(acc[mt][nt][2], acc[mt][nt][3]);
        }
    }
}

// ---------------------------------------------------------------------------
// K2: gather P rows + bias + ReLU + W2 dot + b2. One block (128 thr) per row.
// ---------------------------------------------------------------------------
__global__ void __launch_bounds__(128) gather2_kernel(
    const int* __restrict__ white, const int* __restrict__ black,
    const int* __restrict__ stm,
    const float* __restrict__ b1, const float* __restrict__ W2,
    const float* __restrict__ b2, float* __restrict__ out)
{
    const int r = blockIdx.x;
    const int j = threadIdx.x;
    const int wid = j >> 5, lane = j & 31;

    __shared__ int sW[LFEAT], sB[LFEAT];
    __shared__ float red[4];
    if (j < LFEAT) sW[j] = white[r * LFEAT + j];
    else if (j < 2 * LFEAT) sB[j - LFEAT] = black[r * LFEAT + (j - LFEAT)];
    __syncthreads();

    const int sgn = stm[r];
    const int* first  = sgn ? sW : sB;
    const int* second = sgn ? sB : sW;

    float h = 0.f;
    #pragma unroll 8
    for (int l = 0; l < LFEAT; l++) {
        int f = first[l];
        if (f != 0 && (unsigned)f < NFEAT) h += __ldg(g_P + (size_t)f * POUT + j);
    }
    #pragma unroll 8
    for (int l = 0; l < LFEAT; l++) {
        int f = second[l];
        if (f != 0 && (unsigned)f < NFEAT) h += __ldg(g_P + (size_t)f * POUT + 128 + j);
    }
    h += __ldg(b1 + j);
    h = fmaxf(h, 0.f);
    float p = h * __ldg(W2 + j);
    #pragma unroll
    for (int o = 16; o > 0; o >>= 1) p += __shfl_xor_sync(0xffffffffu, p, o);
    if (lane == 0) red[wid] = p;
    __syncthreads();
    if (j == 0) out[r] = red[0] + red[1] + red[2] + red[3] + b2[0];
}

// ---------------------------------------------------------------------------
extern "C" void kernel_launch(void* const* d_in, const int* in_sizes, int n_in,
                              void* d_out, int out_size)
{
    const int* white = (const int*)d_in[0];
    const int* black = (const int*)d_in[1];
    const int* stm   = (const int*)d_in[2];
    const float* emb = (const float*)d_in[3];
    const float* W1  = (const float*)d_in[4];
    const float* b1  = (const float*)d_in[5];
    const float* W2  = (const float*)d_in[6];
    const float* b2  = (const float*)d_in[7];
    float* out = (float*)d_out;

    // Idempotent, non-stream, capture-safe host call (no static state).
    cudaFuncSetAttribute(pgemm_kernel,
                         cudaFuncAttributeMaxDynamicSharedMemorySize, SMEM_SZ);

    splitW1_kernel<<<POUT * 4096 / (256 * 16), 256>>>(W1);   // 256 blocks
    pgemm_kernel<<<NFEAT / BM, 256, SMEM_SZ>>>(emb);         // 320 blocks
    gather2_kernel<<<BATCH, 128>>>(white, black, stm, b1, W2, b2, out);
}